// round 3
// baseline (speedup 1.0000x reference)
#include <cuda_runtime.h>
#include <cstdint>

#define BB   8192
#define TT   128
#define HID  64
#define NTH  192   // 192 output rows of the 3H gate pre-activations

// Packed fp32x2 FMA: d = a*b + d (FFMA2, only emitted via PTX fma.rn.f32x2)
__device__ __forceinline__ void ffma2(unsigned long long &d,
                                      unsigned long long a,
                                      unsigned long long b) {
    asm("fma.rn.f32x2 %0, %1, %2, %0;" : "+l"(d) : "l"(a), "l"(b));
}
__device__ __forceinline__ float lo32(unsigned long long v) {
    return __uint_as_float((unsigned)v);
}
__device__ __forceinline__ float hi32(unsigned long long v) {
    return __uint_as_float((unsigned)(v >> 32));
}

__device__ __forceinline__ float sigm_fast(float x) {
    return __fdividef(1.f, 1.f + __expf(-x));
}
__device__ __forceinline__ float tanh_fast(float x) {
    // tanh(x) = 1 - 2/(e^{2x}+1); saturates correctly for |x| large
    return 1.f - 2.f * __fdividef(1.f, __expf(2.f * x) + 1.f);
}

__global__ __launch_bounds__(NTH, 2)
void gru_seq_kernel(const int*  __restrict__ actor,
                    const int*  __restrict__ action,
                    const int*  __restrict__ street,
                    const float* __restrict__ bet,
                    const int*  __restrict__ mask,            // bool->int32 [B,T]
                    const float* __restrict__ E_actor,        // [7,8]
                    const float* __restrict__ E_action,       // [4,8]
                    const float* __restrict__ E_street,       // [5,4]
                    const float* __restrict__ W_proj,         // [32,21]
                    const float* __restrict__ b_proj,         // [32]
                    const float* __restrict__ W_ih,           // [192,32]
                    const float* __restrict__ W_hh,           // [192,64]
                    const float* __restrict__ b_ih,           // [192]
                    const float* __restrict__ b_hh,           // [192]
                    float* __restrict__ out)                  // [B,64]
{
    __shared__ __align__(16) float EA[56];      // 7*8
    __shared__ __align__(16) float EAc[32];     // 4*8
    __shared__ __align__(16) float ES[20];      // 5*4
    __shared__ __align__(16) float WP[672];     // 32*21
    __shared__ __align__(16) float bP[32];
    __shared__ __align__(16) float x_s[TT * 32];  // projected inputs, 16 KB
    __shared__ __align__(16) float h_s[HID];
    __shared__ __align__(16) float a_s[NTH];      // xg+hg pre-activations
    __shared__ __align__(16) float hn_s[HID];     // hidden-side n-gate term

    const int j = threadIdx.x;          // output row 0..191
    const int b = blockIdx.x;           // sequence id

    // ---- load small constants to shared ----
    for (int i = j; i < 56;  i += NTH) EA[i]  = E_actor[i];
    for (int i = j; i < 32;  i += NTH) EAc[i] = E_action[i];
    for (int i = j; i < 20;  i += NTH) ES[i]  = E_street[i];
    for (int i = j; i < 672; i += NTH) WP[i]  = W_proj[i];
    for (int i = j; i < 32;  i += NTH) bP[i]  = b_proj[i];
    if (j < HID) h_s[j] = 0.f;

    // ---- per-thread weight rows in registers (packed as f32x2) ----
    unsigned long long wih[16], whh[32];
    {
        const unsigned long long* p1 =
            (const unsigned long long*)(W_ih + j * 32);
        #pragma unroll
        for (int i = 0; i < 16; i++) wih[i] = p1[i];
        const unsigned long long* p2 =
            (const unsigned long long*)(W_hh + j * 64);
        #pragma unroll
        for (int i = 0; i < 32; i++) whh[i] = p2[i];
    }
    const float bihj = b_ih[j];
    const float bhhj = b_hh[j];

    // ---- sequence length from prefix-valid mask (also acts as barrier) ----
    // mask is a JAX bool promoted to int32 by the harness (only f32/i32/bf16
    // dtypes exist there) -> read whole int32 words.
    const int len = __syncthreads_count((j < TT) && (mask[b * TT + j] != 0));

    // ---- precompute x_t = W_proj @ feats_t + b_proj for all valid t ----
    {
        const int w = j >> 5;    // warp 0..5 -> timestep stripes
        const int l = j & 31;    // lane -> x column
        const float* wp = WP + l * 21;
        for (int t = w; t < len; t += NTH / 32) {
            const int   a  = actor [b * TT + t];
            const int   ac = action[b * TT + t];
            const int   st = street[b * TT + t];
            const float bf = bet   [b * TT + t];
            const float* ea  = EA  + a  * 8;
            const float* eac = EAc + ac * 8;
            const float* es  = ES  + st * 4;
            float acc = bP[l];
            #pragma unroll
            for (int k = 0; k < 8; k++) acc += wp[k]      * ea[k];
            #pragma unroll
            for (int k = 0; k < 8; k++) acc += wp[8 + k]  * eac[k];
            #pragma unroll
            for (int k = 0; k < 4; k++) acc += wp[16 + k] * es[k];
            acc += wp[20] * bf;
            x_s[t * 32 + l] = acc;
        }
    }
    __syncthreads();

    // ---- recurrent loop ----
    const unsigned long long* hp = (const unsigned long long*)h_s;
    for (int t = 0; t < len; t++) {
        const unsigned long long* xp =
            (const unsigned long long*)(x_s + t * 32);

        unsigned long long a0 = 0ull, a1 = 0ull;   // W_hh @ h
        unsigned long long c0 = 0ull, c1 = 0ull;   // W_ih @ x
        #pragma unroll
        for (int i = 0; i < 32; i += 2) {
            ffma2(a0, whh[i],     hp[i]);
            ffma2(a1, whh[i + 1], hp[i + 1]);
        }
        #pragma unroll
        for (int i = 0; i < 16; i += 2) {
            ffma2(c0, wih[i],     xp[i]);
            ffma2(c1, wih[i + 1], xp[i + 1]);
        }
        const float gh = bhhj + ((lo32(a0) + hi32(a0)) + (lo32(a1) + hi32(a1)));
        const float gx = bihj + ((lo32(c0) + hi32(c0)) + (lo32(c1) + hi32(c1)));

        a_s[j] = gx + gh;
        if (j >= 128) hn_s[j - 128] = gh;   // hidden-side n term (incl. b_hh)
        __syncthreads();

        if (j < HID) {
            const float r  = sigm_fast(a_s[j]);
            const float z  = sigm_fast(a_s[j + 64]);
            const float hn = hn_s[j];
            // a_s[j+128] = xn + hn  ->  xn + r*hn = a_s + (r-1)*hn
            const float n  = tanh_fast(a_s[j + 128] + (r - 1.f) * hn);
            h_s[j] = (1.f - z) * n + z * h_s[j];
        }
        __syncthreads();
    }

    if (j < HID) out[(long long)b * HID + j] = h_s[j];
}

extern "C" void kernel_launch(void* const* d_in, const int* in_sizes, int n_in,
                              void* d_out, int out_size) {
    const int*   actor    = (const int*)  d_in[0];
    const int*   action   = (const int*)  d_in[1];
    const int*   street   = (const int*)  d_in[2];
    const float* bet      = (const float*)d_in[3];
    const int*   mask     = (const int*)  d_in[4];
    const float* E_actor  = (const float*)d_in[5];
    const float* E_action = (const float*)d_in[6];
    const float* E_street = (const float*)d_in[7];
    const float* W_proj   = (const float*)d_in[8];
    const float* b_proj   = (const float*)d_in[9];
    const float* W_ih     = (const float*)d_in[10];
    const float* W_hh     = (const float*)d_in[11];
    const float* b_ih     = (const float*)d_in[12];
    const float* b_hh     = (const float*)d_in[13];
    float*       out      = (float*)      d_out;

    gru_seq_kernel<<<BB, NTH>>>(actor, action, street, bet, mask,
                                E_actor, E_action, E_street,
                                W_proj, b_proj, W_ih, W_hh, b_ih, b_hh, out);
}

// round 4
// speedup vs baseline: 1.1947x; 1.1947x over previous
#include <cuda_runtime.h>
#include <cstdint>

#define BB   8192
#define TT   128
#define HID  64
#define NTH  96    // each thread owns gate rows j and j+96 (192 rows total)

// Packed fp32x2 FMA: d = a*b + d (FFMA2, only emitted via PTX fma.rn.f32x2)
__device__ __forceinline__ void ffma2(unsigned long long &d,
                                      unsigned long long a,
                                      unsigned long long b) {
    asm("fma.rn.f32x2 %0, %1, %2, %0;" : "+l"(d) : "l"(a), "l"(b));
}
__device__ __forceinline__ float lo32(unsigned long long v) {
    return __uint_as_float((unsigned)v);
}
__device__ __forceinline__ float hi32(unsigned long long v) {
    return __uint_as_float((unsigned)(v >> 32));
}
__device__ __forceinline__ float red2(unsigned long long v) {
    return lo32(v) + hi32(v);
}

__device__ __forceinline__ float sigm_fast(float x) {
    return __fdividef(1.f, 1.f + __expf(-x));
}
__device__ __forceinline__ float tanh_fast(float x) {
    return 1.f - 2.f * __fdividef(1.f, __expf(2.f * x) + 1.f);
}

__global__ __launch_bounds__(NTH, 2)
void gru_seq_kernel(const int*  __restrict__ actor,
                    const int*  __restrict__ action,
                    const int*  __restrict__ street,
                    const float* __restrict__ bet,
                    const int*  __restrict__ mask,            // bool->int32 [B,T]
                    const float* __restrict__ E_actor,        // [7,8]
                    const float* __restrict__ E_action,       // [4,8]
                    const float* __restrict__ E_street,       // [5,4]
                    const float* __restrict__ W_proj,         // [32,21]
                    const float* __restrict__ b_proj,         // [32]
                    const float* __restrict__ W_ih,           // [192,32]
                    const float* __restrict__ W_hh,           // [192,64]
                    const float* __restrict__ b_ih,           // [192]
                    const float* __restrict__ b_hh,           // [192]
                    float* __restrict__ out)                  // [B,64]
{
    __shared__ __align__(16) float EA[56];      // 7*8
    __shared__ __align__(16) float EAc[32];     // 4*8
    __shared__ __align__(16) float ES[20];      // 5*4
    __shared__ __align__(16) float WP[672];     // 32*21
    __shared__ __align__(16) float bP[32];
    __shared__ __align__(16) float x_s[TT * 32];  // projected inputs, 16 KB
    __shared__ __align__(16) float h_s[HID];
    __shared__ __align__(16) float a_s[192];      // xg+hg pre-activations
    __shared__ __align__(16) float hn_s[HID];     // hidden-side n-gate term

    const int j = threadIdx.x;          // thread owns rows j and j+96
    const int b = blockIdx.x;           // sequence id

    // ---- load small constants to shared ----
    for (int i = j; i < 56;  i += NTH) EA[i]  = E_actor[i];
    for (int i = j; i < 32;  i += NTH) EAc[i] = E_action[i];
    for (int i = j; i < 20;  i += NTH) ES[i]  = E_street[i];
    for (int i = j; i < 672; i += NTH) WP[i]  = W_proj[i];
    for (int i = j; i < 32;  i += NTH) bP[i]  = b_proj[i];
    if (j < HID) h_s[j] = 0.f;

    const int rA = j;
    const int rB = j + 96;

    // ---- per-thread weight rows in registers, packed as f32x2 pairs ----
    ulonglong2 wihA[8], wihB[8], whhA[16], whhB[16];
    {
        const ulonglong2* pA = (const ulonglong2*)(W_ih + rA * 32);
        const ulonglong2* pB = (const ulonglong2*)(W_ih + rB * 32);
        #pragma unroll
        for (int i = 0; i < 8; i++) { wihA[i] = pA[i]; wihB[i] = pB[i]; }
        const ulonglong2* qA = (const ulonglong2*)(W_hh + rA * 64);
        const ulonglong2* qB = (const ulonglong2*)(W_hh + rB * 64);
        #pragma unroll
        for (int i = 0; i < 16; i++) { whhA[i] = qA[i]; whhB[i] = qB[i]; }
    }
    const float biA = b_ih[rA], bhA = b_hh[rA];
    const float biB = b_ih[rB], bhB = b_hh[rB];

    // ---- sequence length from prefix-valid mask (int32 words) ----
    // Block has 96 threads; cover t in [0,96) and [96,128) in two counts.
    const int c1 = __syncthreads_count(mask[b * TT + j] != 0);
    const int c2 = __syncthreads_count((j < TT - NTH) &&
                                       (mask[b * TT + NTH + j] != 0));
    const int len = c1 + c2;

    // ---- precompute x_t = W_proj @ feats_t + b_proj for all valid t ----
    {
        const int w = j >> 5;    // warp 0..2 -> timestep stripes
        const int l = j & 31;    // lane -> x column
        const float* wp = WP + l * 21;
        for (int t = w; t < len; t += NTH / 32) {
            const int   a  = actor [b * TT + t];
            const int   ac = action[b * TT + t];
            const int   st = street[b * TT + t];
            const float bf = bet   [b * TT + t];
            const float* ea  = EA  + a  * 8;
            const float* eac = EAc + ac * 8;
            const float* es  = ES  + st * 4;
            float acc = bP[l];
            #pragma unroll
            for (int k = 0; k < 8; k++) acc += wp[k]      * ea[k];
            #pragma unroll
            for (int k = 0; k < 8; k++) acc += wp[8 + k]  * eac[k];
            #pragma unroll
            for (int k = 0; k < 4; k++) acc += wp[16 + k] * es[k];
            acc += wp[20] * bf;
            x_s[t * 32 + l] = acc;
        }
    }
    __syncthreads();

    // ---- recurrent loop ----
    const ulonglong2* hp = (const ulonglong2*)h_s;
    for (int t = 0; t < len; t++) {
        const ulonglong2* xp = (const ulonglong2*)(x_s + t * 32);

        // W_hh @ h for rows A and B (4 accumulator chains each, depth 8)
        unsigned long long hA0 = 0, hA1 = 0, hA2 = 0, hA3 = 0;
        unsigned long long hB0 = 0, hB1 = 0, hB2 = 0, hB3 = 0;
        #pragma unroll
        for (int i = 0; i < 16; i += 2) {
            const ulonglong2 h0 = hp[i];
            const ulonglong2 h1 = hp[i + 1];
            ffma2(hA0, whhA[i].x,     h0.x);
            ffma2(hA1, whhA[i].y,     h0.y);
            ffma2(hA2, whhA[i + 1].x, h1.x);
            ffma2(hA3, whhA[i + 1].y, h1.y);
            ffma2(hB0, whhB[i].x,     h0.x);
            ffma2(hB1, whhB[i].y,     h0.y);
            ffma2(hB2, whhB[i + 1].x, h1.x);
            ffma2(hB3, whhB[i + 1].y, h1.y);
        }
        // W_ih @ x for rows A and B (2 chains each, depth 8)
        unsigned long long xA0 = 0, xA1 = 0, xB0 = 0, xB1 = 0;
        #pragma unroll
        for (int i = 0; i < 8; i++) {
            const ulonglong2 xv = xp[i];
            ffma2(xA0, wihA[i].x, xv.x);
            ffma2(xA1, wihA[i].y, xv.y);
            ffma2(xB0, wihB[i].x, xv.x);
            ffma2(xB1, wihB[i].y, xv.y);
        }

        const float ghA = bhA + ((red2(hA0) + red2(hA1)) + (red2(hA2) + red2(hA3)));
        const float ghB = bhB + ((red2(hB0) + red2(hB1)) + (red2(hB2) + red2(hB3)));
        const float gxA = biA + (red2(xA0) + red2(xA1));
        const float gxB = biB + (red2(xB0) + red2(xB1));

        a_s[rA] = gxA + ghA;
        a_s[rB] = gxB + ghB;
        if (rB >= 128) hn_s[rB - 128] = ghB;   // hidden-side n term (incl. b_hh)
        __syncthreads();

        if (j < HID) {
            const float r  = sigm_fast(a_s[j]);
            const float z  = sigm_fast(a_s[j + 64]);
            const float hn = hn_s[j];
            // a_s[j+128] = xn + hn  ->  xn + r*hn = a_s + (r-1)*hn
            const float n  = tanh_fast(a_s[j + 128] + (r - 1.f) * hn);
            h_s[j] = (1.f - z) * n + z * h_s[j];
        }
        __syncthreads();
    }

    if (j < HID) out[(long long)b * HID + j] = h_s[j];
}

extern "C" void kernel_launch(void* const* d_in, const int* in_sizes, int n_in,
                              void* d_out, int out_size) {
    const int*   actor    = (const int*)  d_in[0];
    const int*   action   = (const int*)  d_in[1];
    const int*   street   = (const int*)  d_in[2];
    const float* bet      = (const float*)d_in[3];
    const int*   mask     = (const int*)  d_in[4];
    const float* E_actor  = (const float*)d_in[5];
    const float* E_action = (const float*)d_in[6];
    const float* E_street = (const float*)d_in[7];
    const float* W_proj   = (const float*)d_in[8];
    const float* b_proj   = (const float*)d_in[9];
    const float* W_ih     = (const float*)d_in[10];
    const float* W_hh     = (const float*)d_in[11];
    const float* b_ih     = (const float*)d_in[12];
    const float* b_hh     = (const float*)d_in[13];
    float*       out      = (float*)      d_out;

    gru_seq_kernel<<<BB, NTH>>>(actor, action, street, bet, mask,
                                E_actor, E_action, E_street,
                                W_proj, b_proj, W_ih, W_hh, b_ih, b_hh, out);
}

// round 5
// speedup vs baseline: 1.8729x; 1.5676x over previous
#include <cuda_runtime.h>
#include <cstdint>

#define BB   8192
#define TT   128
#define HID  64
#define NTH  96    // each thread owns gate rows j and j+96 (192 rows total)

// Precomputed input-path tables (filled by precompute_tables kernel).
// gTA[a*192+r]  = sum_c M[r][c]*E_actor[a][c] + b_ih[r] + (W_ih@b_proj)[r]
// gTAS[(ac*5+st)*192+r] = action+street contributions
// gWbet[r] = M[r][20]
__device__ float gTA[7 * 192];
__device__ float gTAS[20 * 192];
__device__ float gWbet[192];

// Packed fp32x2 FMA: d = a*b + d (FFMA2, only emitted via PTX fma.rn.f32x2)
__device__ __forceinline__ void ffma2(unsigned long long &d,
                                      unsigned long long a,
                                      unsigned long long b) {
    asm("fma.rn.f32x2 %0, %1, %2, %0;" : "+l"(d) : "l"(a), "l"(b));
}
__device__ __forceinline__ float lo32(unsigned long long v) {
    return __uint_as_float((unsigned)v);
}
__device__ __forceinline__ float hi32(unsigned long long v) {
    return __uint_as_float((unsigned)(v >> 32));
}
__device__ __forceinline__ float red2(unsigned long long v) {
    return lo32(v) + hi32(v);
}

__device__ __forceinline__ float sigm_fast(float x) {
    return __fdividef(1.f, 1.f + __expf(-x));
}
__device__ __forceinline__ float tanh_fast(float x) {
    return 1.f - 2.f * __fdividef(1.f, __expf(2.f * x) + 1.f);
}

// One block of 192 threads; thread r computes row r of all tables.
__global__ void precompute_tables(const float* __restrict__ E_actor,   // [7,8]
                                  const float* __restrict__ E_action,  // [4,8]
                                  const float* __restrict__ E_street,  // [5,4]
                                  const float* __restrict__ W_proj,    // [32,21]
                                  const float* __restrict__ b_proj,    // [32]
                                  const float* __restrict__ W_ih,      // [192,32]
                                  const float* __restrict__ b_ih)      // [192]
{
    const int r = threadIdx.x;   // 0..191
    // M[r][c] = sum_i W_ih[r][i] * W_proj[i][c]
    float M[21];
    #pragma unroll
    for (int c = 0; c < 21; c++) {
        float s = 0.f;
        for (int i = 0; i < 32; i++) s += W_ih[r * 32 + i] * W_proj[i * 21 + c];
        M[c] = s;
    }
    float b0 = b_ih[r];
    for (int i = 0; i < 32; i++) b0 += W_ih[r * 32 + i] * b_proj[i];

    for (int a = 0; a < 7; a++) {
        float s = b0;
        #pragma unroll
        for (int c = 0; c < 8; c++) s += M[c] * E_actor[a * 8 + c];
        gTA[a * 192 + r] = s;
    }
    for (int ac = 0; ac < 4; ac++) {
        float sa = 0.f;
        #pragma unroll
        for (int c = 0; c < 8; c++) sa += M[8 + c] * E_action[ac * 8 + c];
        for (int st = 0; st < 5; st++) {
            float s = sa;
            #pragma unroll
            for (int c = 0; c < 4; c++) s += M[16 + c] * E_street[st * 4 + c];
            gTAS[(ac * 5 + st) * 192 + r] = s;
        }
    }
    gWbet[r] = M[20];
}

__global__ __launch_bounds__(NTH, 4)
void gru_seq_kernel(const int*  __restrict__ actor,
                    const int*  __restrict__ action,
                    const int*  __restrict__ street,
                    const float* __restrict__ bet,
                    const int*  __restrict__ mask,            // bool->int32 [B,T]
                    const float* __restrict__ W_hh,           // [192,64]
                    const float* __restrict__ b_hh,           // [192]
                    float* __restrict__ out)                  // [B,64]
{
    __shared__ __align__(16) float TA_s[7 * 192];
    __shared__ __align__(16) float TAS_s[20 * 192];
    __shared__ __align__(16) float wbet_s[192];
    __shared__ __align__(16) float h_s[HID];
    __shared__ __align__(16) float a_s[192];      // xg+hg pre-activations
    __shared__ __align__(16) float hn_s[HID];     // hidden-side n-gate term
    __shared__ int   aoff_s[TT];
    __shared__ int   coff_s[TT];
    __shared__ float bet_s[TT];

    const int j = threadIdx.x;          // thread owns rows j and j+96
    const int b = blockIdx.x;           // sequence id
    const int rA = j;
    const int rB = j + 96;

    // ---- load tables to shared (vectorized; all sizes %4 == 0) ----
    {
        const float4* src1 = (const float4*)gTA;
        float4*       dst1 = (float4*)TA_s;
        for (int i = j; i < 7 * 192 / 4; i += NTH) dst1[i] = src1[i];
        const float4* src2 = (const float4*)gTAS;
        float4*       dst2 = (float4*)TAS_s;
        for (int i = j; i < 20 * 192 / 4; i += NTH) dst2[i] = src2[i];
        const float4* src3 = (const float4*)gWbet;
        float4*       dst3 = (float4*)wbet_s;
        for (int i = j; i < 192 / 4; i += NTH) dst3[i] = src3[i];
    }
    if (j < HID) h_s[j] = 0.f;

    // ---- per-thread W_hh rows in registers, packed as f32x2 pairs ----
    ulonglong2 whhA[16], whhB[16];
    {
        const ulonglong2* qA = (const ulonglong2*)(W_hh + rA * 64);
        const ulonglong2* qB = (const ulonglong2*)(W_hh + rB * 64);
        #pragma unroll
        for (int i = 0; i < 16; i++) { whhA[i] = qA[i]; whhB[i] = qB[i]; }
    }
    const float bhA = b_hh[rA];
    const float bhB = b_hh[rB];

    // ---- sequence length from prefix-valid mask (int32 words) ----
    const int c1 = __syncthreads_count(mask[b * TT + j] != 0);
    const int c2 = __syncthreads_count((j < TT - NTH) &&
                                       (mask[b * TT + NTH + j] != 0));
    const int len = c1 + c2;

    // ---- stage per-step table offsets + bet ----
    for (int t = j; t < len; t += NTH) {
        aoff_s[t] = actor[b * TT + t] * 192;
        coff_s[t] = (action[b * TT + t] * 5 + street[b * TT + t]) * 192;
        bet_s[t]  = bet[b * TT + t];
    }
    __syncthreads();

    // ---- recurrent loop ----
    const ulonglong2* hp = (const ulonglong2*)h_s;
    for (int t = 0; t < len; t++) {
        // W_hh @ h for rows A and B (4 accumulator chains each)
        unsigned long long hA0 = 0, hA1 = 0, hA2 = 0, hA3 = 0;
        unsigned long long hB0 = 0, hB1 = 0, hB2 = 0, hB3 = 0;
        #pragma unroll
        for (int i = 0; i < 16; i += 2) {
            const ulonglong2 h0 = hp[i];
            const ulonglong2 h1 = hp[i + 1];
            ffma2(hA0, whhA[i].x,     h0.x);
            ffma2(hA1, whhA[i].y,     h0.y);
            ffma2(hA2, whhA[i + 1].x, h1.x);
            ffma2(hA3, whhA[i + 1].y, h1.y);
            ffma2(hB0, whhB[i].x,     h0.x);
            ffma2(hB1, whhB[i].y,     h0.y);
            ffma2(hB2, whhB[i + 1].x, h1.x);
            ffma2(hB3, whhB[i + 1].y, h1.y);
        }

        const int   ao = aoff_s[t];
        const int   co = coff_s[t];
        const float bf = bet_s[t];

        const float ghA = bhA + ((red2(hA0) + red2(hA1)) + (red2(hA2) + red2(hA3)));
        const float ghB = bhB + ((red2(hB0) + red2(hB1)) + (red2(hB2) + red2(hB3)));
        const float xgA = TA_s[ao + rA] + TAS_s[co + rA] + wbet_s[rA] * bf;
        const float xgB = TA_s[ao + rB] + TAS_s[co + rB] + wbet_s[rB] * bf;

        a_s[rA] = xgA + ghA;
        a_s[rB] = xgB + ghB;
        if (rB >= 128) hn_s[rB - 128] = ghB;   // n-row hidden-side term (incl. b_hh)
        __syncthreads();

        if (j < HID) {
            const float r  = sigm_fast(a_s[j]);
            const float z  = sigm_fast(a_s[j + 64]);
            const float hn = hn_s[j];
            // a_s[j+128] = xn + hn  ->  xn + r*hn = a_s + (r-1)*hn
            const float n  = tanh_fast(a_s[j + 128] + (r - 1.f) * hn);
            h_s[j] = (1.f - z) * n + z * h_s[j];
        }
        __syncthreads();
    }

    if (j < HID) out[(long long)b * HID + j] = h_s[j];
}

extern "C" void kernel_launch(void* const* d_in, const int* in_sizes, int n_in,
                              void* d_out, int out_size) {
    const int*   actor    = (const int*)  d_in[0];
    const int*   action   = (const int*)  d_in[1];
    const int*   street   = (const int*)  d_in[2];
    const float* bet      = (const float*)d_in[3];
    const int*   mask     = (const int*)  d_in[4];
    const float* E_actor  = (const float*)d_in[5];
    const float* E_action = (const float*)d_in[6];
    const float* E_street = (const float*)d_in[7];
    const float* W_proj   = (const float*)d_in[8];
    const float* b_proj   = (const float*)d_in[9];
    const float* W_ih     = (const float*)d_in[10];
    const float* W_hh     = (const float*)d_in[11];
    const float* b_ih     = (const float*)d_in[12];
    const float* b_hh     = (const float*)d_in[13];
    float*       out      = (float*)      d_out;

    precompute_tables<<<1, 192>>>(E_actor, E_action, E_street,
                                  W_proj, b_proj, W_ih, b_ih);
    gru_seq_kernel<<<BB, NTH>>>(actor, action, street, bet, mask,
                                W_hh, b_hh, out);
}